// round 10
// baseline (speedup 1.0000x reference)
#include <cuda_runtime.h>
#include <cuda_bf16.h>
#include <cstdint>

#define N_NODES 50000
#define N_EDGES 800000
#define IN_F    128
#define OUT_F   256
#define PITCH   136   // bf16 per padded row; 68 words mod 32 = 4 -> conflict-free
#define CAP     64
#define OVF_CAP 1024
#define N_MTILES ((N_NODES + 63) / 64)    // 782 tiles of 64 rows
#define GEMM_GRID 296                      // 148 SMs x 2 CTAs (one per N-half)

// ---------------------------------------------------------------------------
// Device scratch (no allocs allowed)
// ---------------------------------------------------------------------------
__device__ float g_agg[(size_t)N_NODES * IN_F];
__device__ __align__(16) __nv_bfloat16 g_Bhi[OUT_F * PITCH];
__device__ __align__(16) __nv_bfloat16 g_Blo[OUT_F * PITCH];
__device__ int   g_cnt[N_NODES];
__device__ __align__(8)  uint2 g_edge[(size_t)N_NODES * CAP];
__device__ int   g_ovf_cnt;
__device__ __align__(16) uint4 g_ovf[OVF_CAP];

// ---------------------------------------------------------------------------
// K1: zero counts + convert W -> padded bf16 hi/lo images of W^T.
// ---------------------------------------------------------------------------
__global__ void prep_kernel(const float* __restrict__ W) {
    const int tid = blockIdx.x * blockDim.x + threadIdx.x;
    for (int i = tid; i < N_NODES; i += gridDim.x * blockDim.x) g_cnt[i] = 0;
    if (tid == 0) g_ovf_cnt = 0;

    if (blockIdx.x < 32) {
        const int base = (blockIdx.x * 256 + threadIdx.x) * 4;   // idx = k*256+n
        const float4 w = *reinterpret_cast<const float4*>(W + base);
        const float f[4] = {w.x, w.y, w.z, w.w};
        #pragma unroll
        for (int j = 0; j < 4; j++) {
            const int idx = base + j;
            const int k = idx >> 8;
            const int n = idx & 255;
            const __nv_bfloat16 h = __float2bfloat16(f[j]);
            const __nv_bfloat16 l = __float2bfloat16(f[j] - __bfloat162float(h));
            g_Bhi[n * PITCH + k] = h;
            g_Blo[n * PITCH + k] = l;
        }
    }
}

// ---------------------------------------------------------------------------
// K2: direct binning — atomic slot claim, 4 edges/thread for ILP.
// ---------------------------------------------------------------------------
__device__ __forceinline__ void bin_one(int r, int c, float v) {
    const int slot = atomicAdd(&g_cnt[r], 1);
    if (slot < CAP) {
        g_edge[(size_t)r * CAP + slot] = make_uint2((uint32_t)c, __float_as_uint(v));
    } else {
        const int p = atomicAdd(&g_ovf_cnt, 1);
        if (p < OVF_CAP)
            g_ovf[p] = make_uint4((uint32_t)r, (uint32_t)c, __float_as_uint(v), 0u);
    }
}

__global__ void bin_kernel(const int*   __restrict__ erow,
                           const int*   __restrict__ ecol,
                           const float* __restrict__ eval) {
    const int base = (blockIdx.x * blockDim.x + threadIdx.x) * 4;
    if (base + 4 <= N_EDGES) {
        const int4   r = __ldg(reinterpret_cast<const int4*>(erow + base));
        const int4   c = __ldg(reinterpret_cast<const int4*>(ecol + base));
        const float4 v = __ldg(reinterpret_cast<const float4*>(eval + base));
        const int s0 = atomicAdd(&g_cnt[r.x], 1);
        const int s1 = atomicAdd(&g_cnt[r.y], 1);
        const int s2 = atomicAdd(&g_cnt[r.z], 1);
        const int s3 = atomicAdd(&g_cnt[r.w], 1);
        if (s0 < CAP) g_edge[(size_t)r.x * CAP + s0] = make_uint2((uint32_t)c.x, __float_as_uint(v.x));
        if (s1 < CAP) g_edge[(size_t)r.y * CAP + s1] = make_uint2((uint32_t)c.y, __float_as_uint(v.y));
        if (s2 < CAP) g_edge[(size_t)r.z * CAP + s2] = make_uint2((uint32_t)c.z, __float_as_uint(v.z));
        if (s3 < CAP) g_edge[(size_t)r.w * CAP + s3] = make_uint2((uint32_t)c.w, __float_as_uint(v.w));
        if (s0 >= CAP) { const int p = atomicAdd(&g_ovf_cnt, 1); if (p < OVF_CAP) g_ovf[p] = make_uint4((uint32_t)r.x, (uint32_t)c.x, __float_as_uint(v.x), 0u); }
        if (s1 >= CAP) { const int p = atomicAdd(&g_ovf_cnt, 1); if (p < OVF_CAP) g_ovf[p] = make_uint4((uint32_t)r.y, (uint32_t)c.y, __float_as_uint(v.y), 0u); }
        if (s2 >= CAP) { const int p = atomicAdd(&g_ovf_cnt, 1); if (p < OVF_CAP) g_ovf[p] = make_uint4((uint32_t)r.z, (uint32_t)c.z, __float_as_uint(v.z), 0u); }
        if (s3 >= CAP) { const int p = atomicAdd(&g_ovf_cnt, 1); if (p < OVF_CAP) g_ovf[p] = make_uint4((uint32_t)r.w, (uint32_t)c.w, __float_as_uint(v.w), 0u); }
    } else {
        for (int e = base; e < N_EDGES; e++)
            bin_one(__ldg(erow + e), __ldg(ecol + e), __ldg(eval + e));
    }
}

// ---------------------------------------------------------------------------
// K3: gather-aggregate. One warp per row; overflow handled inline.
// ---------------------------------------------------------------------------
__global__ __launch_bounds__(256)
void gather_kernel(const float* __restrict__ x) {
    const int lane = threadIdx.x & 31;
    const int wid  = threadIdx.x >> 5;
    const int row  = blockIdx.x * 8 + wid;
    if (row >= N_NODES) return;

    const int raw_cnt = __ldg(g_cnt + row);
    const int cnt = min(raw_cnt, CAP);
    const size_t base = (size_t)row * CAP;

    float4 acc = make_float4(0.f, 0.f, 0.f, 0.f);

    #pragma unroll
    for (int batch = 0; batch < 2; batch++) {
        const int nb = min(cnt - batch * 32, 32);
        if (nb <= 0) break;
        const uint2 ed = __ldg(g_edge + base + batch * 32 + lane);

        for (int j = 0; j < nb; j += 4) {
            uint32_t c[4];
            float    v[4];
            #pragma unroll
            for (int u = 0; u < 4; u++) {
                const bool valid = (j + u) < nb;
                const uint32_t cc = __shfl_sync(~0u, ed.x, (j + u) & 31);
                const uint32_t vv = __shfl_sync(~0u, ed.y, (j + u) & 31);
                c[u] = valid ? cc : 0u;
                v[u] = valid ? __uint_as_float(vv) : 0.f;
            }
            float4 xv[4];
            #pragma unroll
            for (int u = 0; u < 4; u++)
                xv[u] = __ldg(reinterpret_cast<const float4*>(
                    x + (size_t)c[u] * IN_F) + lane);
            #pragma unroll
            for (int u = 0; u < 4; u++) {
                acc.x += v[u] * xv[u].x;
                acc.y += v[u] * xv[u].y;
                acc.z += v[u] * xv[u].z;
                acc.w += v[u] * xv[u].w;
            }
        }
    }

    if (raw_cnt > CAP) {
        const int n = min(g_ovf_cnt, OVF_CAP);
        for (int i = 0; i < n; i++) {
            const uint4 e = g_ovf[i];
            if ((int)e.x == row) {
                const float v = __uint_as_float(e.z);
                const float4 xv = __ldg(reinterpret_cast<const float4*>(
                    x + (size_t)e.y * IN_F) + lane);
                acc.x += v * xv.x; acc.y += v * xv.y;
                acc.z += v * xv.z; acc.w += v * xv.w;
            }
        }
    }

    *reinterpret_cast<float4*>(g_agg + (size_t)row * IN_F + lane * 4) = acc;
}

// ---------------------------------------------------------------------------
// K4: persistent mma.sync bf16 split GEMM + bias.
// CTA tile 64(M) x 128(N-half); ~103KB smem -> 2 CTAs/SM (32 warps/SM).
// Even CTAs take N[0:128), odd take N[128:256); each loops M tiles.
// ---------------------------------------------------------------------------
#define GT 256
#define SM_BIAS 0                                   // 256 floats (full bias)
#define SM_AHI  1024
#define SM_ALO  (SM_AHI + 64 * PITCH * 2)           // +17408
#define SM_BHI  (SM_ALO + 64 * PITCH * 2)
#define SM_BLO  (SM_BHI + 128 * PITCH * 2)          // +34816
#define SM_TOT  (SM_BLO + 128 * PITCH * 2)          // 105472 B

__device__ __forceinline__ void mma16816(float c[4], uint32_t a0, uint32_t a1,
                                         uint32_t a2, uint32_t a3,
                                         uint32_t b0, uint32_t b1) {
    asm volatile(
        "mma.sync.aligned.m16n8k16.row.col.f32.bf16.bf16.f32 "
        "{%0,%1,%2,%3}, {%4,%5,%6,%7}, {%8,%9}, {%0,%1,%2,%3};"
        : "+f"(c[0]), "+f"(c[1]), "+f"(c[2]), "+f"(c[3])
        : "r"(a0), "r"(a1), "r"(a2), "r"(a3), "r"(b0), "r"(b1));
}

__device__ __forceinline__ void ldmx4(uint32_t& r0, uint32_t& r1,
                                      uint32_t& r2, uint32_t& r3,
                                      uint32_t saddr) {
    asm volatile("ldmatrix.sync.aligned.m8n8.x4.shared.b16 {%0,%1,%2,%3}, [%4];"
                 : "=r"(r0), "=r"(r1), "=r"(r2), "=r"(r3) : "r"(saddr));
}

__device__ __forceinline__ uint32_t smem_u32(const void* p) {
    uint32_t a;
    asm("{ .reg .u64 t; cvta.to.shared.u64 t, %1; cvt.u32.u64 %0, t; }"
        : "=r"(a) : "l"(p));
    return a;
}

__global__ __launch_bounds__(GT, 2)
void gemm_mma_kernel(const float* __restrict__ bias,
                     float*       __restrict__ out) {
    extern __shared__ char smem[];
    const int t    = threadIdx.x;
    const int lane = t & 31;
    const int wid  = t >> 5;
    const int half = blockIdx.x & 1;           // which 128-col N half
    const int ncol0 = half * 128;

    float* bias_s = reinterpret_cast<float*>(smem + SM_BIAS);
    __nv_bfloat16* Ahi = reinterpret_cast<__nv_bfloat16*>(smem + SM_AHI);
    __nv_bfloat16* Alo = reinterpret_cast<__nv_bfloat16*>(smem + SM_ALO);

    if (t < 64)
        reinterpret_cast<float4*>(bias_s)[t] =
            reinterpret_cast<const float4*>(bias)[t];

    // Stage this CTA's B-half images once: 2 x 2176 uint4 (rows ncol0..+127).
    {
        const uint4* sh = reinterpret_cast<const uint4*>(g_Bhi + ncol0 * PITCH);
        const uint4* sl = reinterpret_cast<const uint4*>(g_Blo + ncol0 * PITCH);
        uint4* dh = reinterpret_cast<uint4*>(smem + SM_BHI);
        uint4* dl = reinterpret_cast<uint4*>(smem + SM_BLO);
        #pragma unroll
        for (int i = 0; i < 8; i++) {
            dh[t + i * GT] = sh[t + i * GT];
            dl[t + i * GT] = sl[t + i * GT];
        }
        if (t < 2176 - 8 * GT) {
            dh[t + 8 * GT] = sh[t + 8 * GT];
            dl[t + 8 * GT] = sl[t + 8 * GT];
        }
    }

    // Warp tiling: grid 2(m) x 4(n); warp tile 32x32.
    const int wm = wid >> 2;
    const int wn = wid & 3;
    const int g  = lane >> 2;
    const int tg = lane & 3;
    const int m_base = wm * 32;
    const int n_base = wn * 32;

    // ldmatrix lane address patterns (verified in R9).
    const int a_row = (lane & 7) + ((lane >> 3) & 1) * 8;
    const int a_kof = (lane >> 4) * 8;
    const int b_row = (lane & 7) + ((lane >> 4) & 1) * 8;
    const int b_kof = ((lane >> 3) & 1) * 8;

    const uint32_t sAhi = smem_u32(Ahi);
    const uint32_t sAlo = smem_u32(Alo);
    const uint32_t sBhi = smem_u32(smem + SM_BHI);
    const uint32_t sBlo = smem_u32(smem + SM_BLO);

    uint32_t aOff[2];
    #pragma unroll
    for (int mt = 0; mt < 2; mt++)
        aOff[mt] = ((m_base + mt * 16 + a_row) * PITCH + a_kof) * 2;
    uint32_t bOff[2];
    #pragma unroll
    for (int ntp = 0; ntp < 2; ntp++)
        bOff[ntp] = ((n_base + ntp * 16 + b_row) * PITCH + b_kof) * 2;

    // -------- persistent M-tile loop --------
    for (int tile = blockIdx.x >> 1; tile < N_MTILES; tile += GEMM_GRID / 2) {
        const int rowbase = tile * 64;

        // Stage agg tile [64,128] fp32 -> hi/lo bf16. 1024 items / 256 thr.
        #pragma unroll
        for (int i = 0; i < 4; i++) {
            const int idx = t + i * GT;
            const int kb = idx & 15;
            const int m  = idx >> 4;
            const int row = rowbase + m;

            float f[8];
            if (row < N_NODES) {
                const float4* src = reinterpret_cast<const float4*>(
                    g_agg + (size_t)row * IN_F + kb * 8);
                const float4 u = src[0];
                const float4 v = src[1];
                f[0]=u.x; f[1]=u.y; f[2]=u.z; f[3]=u.w;
                f[4]=v.x; f[5]=v.y; f[6]=v.z; f[7]=v.w;
            } else {
                #pragma unroll
                for (int j = 0; j < 8; j++) f[j] = 0.f;
            }

            uint4 wh, wl;
            uint32_t* ph = reinterpret_cast<uint32_t*>(&wh);
            uint32_t* pl = reinterpret_cast<uint32_t*>(&wl);
            #pragma unroll
            for (int j = 0; j < 4; j++) {
                const __nv_bfloat16 h0 = __float2bfloat16(f[2*j]);
                const __nv_bfloat16 h1 = __float2bfloat16(f[2*j+1]);
                const __nv_bfloat16 l0 = __float2bfloat16(f[2*j]   - __bfloat162float(h0));
                const __nv_bfloat16 l1 = __float2bfloat16(f[2*j+1] - __bfloat162float(h1));
                __nv_bfloat162 hp = __halves2bfloat162(h0, h1);
                __nv_bfloat162 lp = __halves2bfloat162(l0, l1);
                ph[j] = *reinterpret_cast<uint32_t*>(&hp);
                pl[j] = *reinterpret_cast<uint32_t*>(&lp);
            }
            *reinterpret_cast<uint4*>(Ahi + m * PITCH + kb * 8) = wh;
            *reinterpret_cast<uint4*>(Alo + m * PITCH + kb * 8) = wl;
        }
        __syncthreads();

        float acc[2][4][4];
        #pragma unroll
        for (int mt = 0; mt < 2; mt++)
            #pragma unroll
            for (int nt = 0; nt < 4; nt++)
                #pragma unroll
                for (int j = 0; j < 4; j++)
                    acc[mt][nt][j] = 0.f;

        const uint32_t aBase[3] = {sAhi, sAhi, sAlo};
        const uint32_t bBase[3] = {sBhi, sBlo, sBhi};

        #pragma unroll
        for (int pass = 0; pass < 3; pass++) {
            const uint32_t ab = aBase[pass];
            const uint32_t bb = bBase[pass];
            #pragma unroll
            for (int ks = 0; ks < IN_F; ks += 16) {
                uint32_t af[2][4];
                #pragma unroll
                for (int mt = 0; mt < 2; mt++)
                    ldmx4(af[mt][0], af[mt][1], af[mt][2], af[mt][3],
                          ab + aOff[mt] + ks * 2);
                uint32_t bf[4][2];
                #pragma unroll
                for (int ntp = 0; ntp < 2; ntp++)
                    ldmx4(bf[2*ntp][0], bf[2*ntp][1],
                          bf[2*ntp+1][0], bf[2*ntp+1][1],
                          bb + bOff[ntp] + ks * 2);
                #pragma unroll
                for (int mt = 0; mt < 2; mt++)
                    #pragma unroll
                    for (int nt = 0; nt < 4; nt++)
                        mma16816(acc[mt][nt],
                                 af[mt][0], af[mt][1], af[mt][2], af[mt][3],
                                 bf[nt][0], bf[nt][1]);
            }
        }

        // Epilogue
        #pragma unroll
        for (int mt = 0; mt < 2; mt++) {
            const int r0 = rowbase + m_base + mt * 16 + g;
            const int r1 = r0 + 8;
            #pragma unroll
            for (int nt = 0; nt < 4; nt++) {
                const int col = ncol0 + n_base + nt * 8 + tg * 2;
                const float bx = bias_s[col];
                const float by = bias_s[col + 1];
                if (r0 < N_NODES) {
                    float2 o = make_float2(acc[mt][nt][0] + bx, acc[mt][nt][1] + by);
                    *reinterpret_cast<float2*>(out + (size_t)r0 * OUT_F + col) = o;
                }
                if (r1 < N_NODES) {
                    float2 o = make_float2(acc[mt][nt][2] + bx, acc[mt][nt][3] + by);
                    *reinterpret_cast<float2*>(out + (size_t)r1 * OUT_F + col) = o;
                }
            }
        }
        __syncthreads();   // protect Ahi/Alo reuse next tile
    }
}

// ---------------------------------------------------------------------------
// Launch
// ---------------------------------------------------------------------------
extern "C" void kernel_launch(void* const* d_in, const int* in_sizes, int n_in,
                              void* d_out, int out_size) {
    const float* x    = (const float*)d_in[0];
    const int*   erow = (const int*)  d_in[1];
    const int*   ecol = (const int*)  d_in[2];
    const float* eval = (const float*)d_in[3];
    const float* W    = (const float*)d_in[4];
    const float* bias = (const float*)d_in[5];
    float* out = (float*)d_out;

    prep_kernel<<<128, 256>>>(W);
    bin_kernel<<<(N_EDGES / 4 + 255) / 256, 256>>>(erow, ecol, eval);
    gather_kernel<<<(N_NODES + 7) / 8, 256>>>(x);

    cudaFuncSetAttribute(gemm_mma_kernel,
                         cudaFuncAttributeMaxDynamicSharedMemorySize, SM_TOT);
    gemm_mma_kernel<<<GEMM_GRID, GT, SM_TOT>>>(bias, out);
}

// round 11
// speedup vs baseline: 1.7126x; 1.7126x over previous
#include <cuda_runtime.h>
#include <cuda_fp16.h>
#include <cstdint>

#define N_NODES 50000
#define N_EDGES 800000
#define IN_F    128
#define OUT_F   256
#define PITCH   136   // fp16 per padded row; 68 words mod 32 = 4 -> conflict-free
#define CAP     64
#define OVF_CAP 1024

// ---------------------------------------------------------------------------
// Device scratch (no allocs allowed)
// ---------------------------------------------------------------------------
__device__ float g_agg[(size_t)N_NODES * IN_F];
__device__ __align__(16) __half g_Bhi[OUT_F * PITCH];   // W^T fp16 hi image
__device__ __align__(16) __half g_Blo[OUT_F * PITCH];   // W^T fp16 lo image
__device__ int   g_cnt[N_NODES];
__device__ __align__(8)  uint2 g_edge[(size_t)N_NODES * CAP];
__device__ int   g_ovf_cnt;
__device__ __align__(16) uint4 g_ovf[OVF_CAP];

// ---------------------------------------------------------------------------
// K1: zero counts + convert W -> padded fp16 hi/lo images of W^T.
// ---------------------------------------------------------------------------
__global__ void prep_kernel(const float* __restrict__ W) {
    const int tid = blockIdx.x * blockDim.x + threadIdx.x;
    for (int i = tid; i < N_NODES; i += gridDim.x * blockDim.x) g_cnt[i] = 0;
    if (tid == 0) g_ovf_cnt = 0;

    if (blockIdx.x < 32) {
        const int base = (blockIdx.x * 256 + threadIdx.x) * 4;   // idx = k*256+n
        const float4 w = *reinterpret_cast<const float4*>(W + base);
        const float f[4] = {w.x, w.y, w.z, w.w};
        #pragma unroll
        for (int j = 0; j < 4; j++) {
            const int idx = base + j;
            const int k = idx >> 8;
            const int n = idx & 255;
            const __half h = __float2half(f[j]);
            const __half l = __float2half(f[j] - __half2float(h));
            g_Bhi[n * PITCH + k] = h;
            g_Blo[n * PITCH + k] = l;
        }
    }
}

// ---------------------------------------------------------------------------
// K2: direct binning — atomic slot claim, 4 edges/thread for ILP.
// ---------------------------------------------------------------------------
__device__ __forceinline__ void bin_one(int r, int c, float v) {
    const int slot = atomicAdd(&g_cnt[r], 1);
    if (slot < CAP) {
        g_edge[(size_t)r * CAP + slot] = make_uint2((uint32_t)c, __float_as_uint(v));
    } else {
        const int p = atomicAdd(&g_ovf_cnt, 1);
        if (p < OVF_CAP)
            g_ovf[p] = make_uint4((uint32_t)r, (uint32_t)c, __float_as_uint(v), 0u);
    }
}

__global__ void bin_kernel(const int*   __restrict__ erow,
                           const int*   __restrict__ ecol,
                           const float* __restrict__ eval) {
    const int base = (blockIdx.x * blockDim.x + threadIdx.x) * 4;
    if (base + 4 <= N_EDGES) {
        const int4   r = __ldg(reinterpret_cast<const int4*>(erow + base));
        const int4   c = __ldg(reinterpret_cast<const int4*>(ecol + base));
        const float4 v = __ldg(reinterpret_cast<const float4*>(eval + base));
        const int s0 = atomicAdd(&g_cnt[r.x], 1);
        const int s1 = atomicAdd(&g_cnt[r.y], 1);
        const int s2 = atomicAdd(&g_cnt[r.z], 1);
        const int s3 = atomicAdd(&g_cnt[r.w], 1);
        if (s0 < CAP) g_edge[(size_t)r.x * CAP + s0] = make_uint2((uint32_t)c.x, __float_as_uint(v.x));
        if (s1 < CAP) g_edge[(size_t)r.y * CAP + s1] = make_uint2((uint32_t)c.y, __float_as_uint(v.y));
        if (s2 < CAP) g_edge[(size_t)r.z * CAP + s2] = make_uint2((uint32_t)c.z, __float_as_uint(v.z));
        if (s3 < CAP) g_edge[(size_t)r.w * CAP + s3] = make_uint2((uint32_t)c.w, __float_as_uint(v.w));
        if (s0 >= CAP) { const int p = atomicAdd(&g_ovf_cnt, 1); if (p < OVF_CAP) g_ovf[p] = make_uint4((uint32_t)r.x, (uint32_t)c.x, __float_as_uint(v.x), 0u); }
        if (s1 >= CAP) { const int p = atomicAdd(&g_ovf_cnt, 1); if (p < OVF_CAP) g_ovf[p] = make_uint4((uint32_t)r.y, (uint32_t)c.y, __float_as_uint(v.y), 0u); }
        if (s2 >= CAP) { const int p = atomicAdd(&g_ovf_cnt, 1); if (p < OVF_CAP) g_ovf[p] = make_uint4((uint32_t)r.z, (uint32_t)c.z, __float_as_uint(v.z), 0u); }
        if (s3 >= CAP) { const int p = atomicAdd(&g_ovf_cnt, 1); if (p < OVF_CAP) g_ovf[p] = make_uint4((uint32_t)r.w, (uint32_t)c.w, __float_as_uint(v.w), 0u); }
    } else {
        for (int e = base; e < N_EDGES; e++)
            bin_one(__ldg(erow + e), __ldg(ecol + e), __ldg(eval + e));
    }
}

// ---------------------------------------------------------------------------
// K3: gather-aggregate. One warp per row; overflow handled inline.
// ---------------------------------------------------------------------------
__global__ __launch_bounds__(256)
void gather_kernel(const float* __restrict__ x) {
    const int lane = threadIdx.x & 31;
    const int wid  = threadIdx.x >> 5;
    const int row  = blockIdx.x * 8 + wid;
    if (row >= N_NODES) return;

    const int raw_cnt = __ldg(g_cnt + row);
    const int cnt = min(raw_cnt, CAP);
    const size_t base = (size_t)row * CAP;

    float4 acc = make_float4(0.f, 0.f, 0.f, 0.f);

    #pragma unroll
    for (int batch = 0; batch < 2; batch++) {
        const int nb = min(cnt - batch * 32, 32);
        if (nb <= 0) break;
        const uint2 ed = __ldg(g_edge + base + batch * 32 + lane);

        for (int j = 0; j < nb; j += 4) {
            uint32_t c[4];
            float    v[4];
            #pragma unroll
            for (int u = 0; u < 4; u++) {
                const bool valid = (j + u) < nb;
                const uint32_t cc = __shfl_sync(~0u, ed.x, (j + u) & 31);
                const uint32_t vv = __shfl_sync(~0u, ed.y, (j + u) & 31);
                c[u] = valid ? cc : 0u;
                v[u] = valid ? __uint_as_float(vv) : 0.f;
            }
            float4 xv[4];
            #pragma unroll
            for (int u = 0; u < 4; u++)
                xv[u] = __ldg(reinterpret_cast<const float4*>(
                    x + (size_t)c[u] * IN_F) + lane);
            #pragma unroll
            for (int u = 0; u < 4; u++) {
                acc.x += v[u] * xv[u].x;
                acc.y += v[u] * xv[u].y;
                acc.z += v[u] * xv[u].z;
                acc.w += v[u] * xv[u].w;
            }
        }
    }

    if (raw_cnt > CAP) {
        const int n = min(g_ovf_cnt, OVF_CAP);
        for (int i = 0; i < n; i++) {
            const uint4 e = g_ovf[i];
            if ((int)e.x == row) {
                const float v = __uint_as_float(e.z);
                const float4 xv = __ldg(reinterpret_cast<const float4*>(
                    x + (size_t)e.y * IN_F) + lane);
                acc.x += v * xv.x; acc.y += v * xv.y;
                acc.z += v * xv.z; acc.w += v * xv.w;
            }
        }
    }

    *reinterpret_cast<float4*>(g_agg + (size_t)row * IN_F + lane * 4) = acc;
}

// ---------------------------------------------------------------------------
// K4: mma.sync fp16 2-pass GEMM + bias (R7 structure: 256 thr, 64x64 warp
// tiles, scalar fragment loads — pipe-bound, so spills are irrelevant).
//   out = A@Bhi + A@Blo + b    (A = fp16(agg), B fp16 hi/lo, fp32 accum)
// ---------------------------------------------------------------------------
#define GT 256
#define SM_BIAS 0
#define SM_A    1024
#define SM_BHI  (SM_A   + 128 * PITCH * 2)          // +34816
#define SM_BLO  (SM_BHI + OUT_F * PITCH * 2)        // +69632
#define SM_TOT  (SM_BLO + OUT_F * PITCH * 2)        // 175104 B

__device__ __forceinline__ void mma16816(float c[4], uint32_t a0, uint32_t a1,
                                         uint32_t a2, uint32_t a3,
                                         uint32_t b0, uint32_t b1) {
    asm volatile(
        "mma.sync.aligned.m16n8k16.row.col.f32.f16.f16.f32 "
        "{%0,%1,%2,%3}, {%4,%5,%6,%7}, {%8,%9}, {%0,%1,%2,%3};"
        : "+f"(c[0]), "+f"(c[1]), "+f"(c[2]), "+f"(c[3])
        : "r"(a0), "r"(a1), "r"(a2), "r"(a3), "r"(b0), "r"(b1));
}

__global__ __launch_bounds__(GT, 1)
void gemm_mma_kernel(const float* __restrict__ bias,
                     float*       __restrict__ out) {
    extern __shared__ char smem[];
    const int t    = threadIdx.x;
    const int lane = t & 31;
    const int wid  = t >> 5;
    const int rowbase = blockIdx.x * 128;

    float* bias_s = reinterpret_cast<float*>(smem + SM_BIAS);
    __half* As  = reinterpret_cast<__half*>(smem + SM_A);
    __half* Bhi = reinterpret_cast<__half*>(smem + SM_BHI);
    __half* Blo = reinterpret_cast<__half*>(smem + SM_BLO);

    if (t < 64)
        reinterpret_cast<float4*>(bias_s)[t] =
            reinterpret_cast<const float4*>(bias)[t];

    // Copy W^T hi/lo images: 2 x 4352 uint4, 17 per thread each.
    {
        const uint4* sh = reinterpret_cast<const uint4*>(g_Bhi);
        const uint4* sl = reinterpret_cast<const uint4*>(g_Blo);
        uint4* dh = reinterpret_cast<uint4*>(Bhi);
        uint4* dl = reinterpret_cast<uint4*>(Blo);
        #pragma unroll
        for (int i = 0; i < 17; i++) {
            dh[t + i * GT] = sh[t + i * GT];
            dl[t + i * GT] = sl[t + i * GT];
        }
    }

    // Stage agg tile [128,128] fp32 -> single fp16 image.
    // item = (m, kb): kb = 8-wide k block. 2048 items / 256 thr = 8 each.
    #pragma unroll
    for (int i = 0; i < 8; i++) {
        const int idx = t + i * GT;
        const int kb = idx & 15;
        const int m  = idx >> 4;
        const int row = rowbase + m;

        float f[8];
        if (row < N_NODES) {
            const float4* src = reinterpret_cast<const float4*>(
                g_agg + (size_t)row * IN_F + kb * 8);
            const float4 u = src[0];
            const float4 v = src[1];
            f[0]=u.x; f[1]=u.y; f[2]=u.z; f[3]=u.w;
            f[4]=v.x; f[5]=v.y; f[6]=v.z; f[7]=v.w;
        } else {
            #pragma unroll
            for (int j = 0; j < 8; j++) f[j] = 0.f;
        }

        uint4 wa;
        uint32_t* pa = reinterpret_cast<uint32_t*>(&wa);
        #pragma unroll
        for (int j = 0; j < 4; j++) {
            __half2 hp = __floats2half2_rn(f[2*j], f[2*j+1]);
            pa[j] = *reinterpret_cast<uint32_t*>(&hp);
        }
        *reinterpret_cast<uint4*>(As + m * PITCH + kb * 8) = wa;
    }
    __syncthreads();

    // Warp grid 2(m) x 4(n); warp tile 64x64.
    const int wm = wid >> 2;
    const int wn = wid & 3;
    const int g  = lane >> 2;
    const int tg = lane & 3;
    const int m_base = wm * 64;
    const int n_base = wn * 64;

    float acc[4][8][4];
    #pragma unroll
    for (int mt = 0; mt < 4; mt++)
        #pragma unroll
        for (int nt = 0; nt < 8; nt++)
            #pragma unroll
            for (int j = 0; j < 4; j++)
                acc[mt][nt][j] = 0.f;

    const __half* Bp[2] = {Bhi, Blo};

    #pragma unroll
    for (int pass = 0; pass < 2; pass++) {
        const __half* B = Bp[pass];
        #pragma unroll
        for (int ks = 0; ks < IN_F; ks += 16) {
            uint32_t af[4][4];
            #pragma unroll
            for (int mt = 0; mt < 4; mt++) {
                const __half* ar =
                    As + (m_base + mt * 16 + g) * PITCH + ks + tg * 2;
                af[mt][0] = *reinterpret_cast<const uint32_t*>(ar);
                af[mt][1] = *reinterpret_cast<const uint32_t*>(ar + 8 * PITCH);
                af[mt][2] = *reinterpret_cast<const uint32_t*>(ar + 8);
                af[mt][3] = *reinterpret_cast<const uint32_t*>(ar + 8 * PITCH + 8);
            }
            uint32_t bf[8][2];
            #pragma unroll
            for (int nt = 0; nt < 8; nt++) {
                const __half* br =
                    B + (n_base + nt * 8 + g) * PITCH + ks + tg * 2;
                bf[nt][0] = *reinterpret_cast<const uint32_t*>(br);
                bf[nt][1] = *reinterpret_cast<const uint32_t*>(br + 8);
            }
            #pragma unroll
            for (int mt = 0; mt < 4; mt++)
                #pragma unroll
                for (int nt = 0; nt < 8; nt++)
                    mma16816(acc[mt][nt],
                             af[mt][0], af[mt][1], af[mt][2], af[mt][3],
                             bf[nt][0], bf[nt][1]);
        }
    }

    // Epilogue: c0:(g,2t) c1:(g,2t+1) c2:(g+8,2t) c3:(g+8,2t+1)
    #pragma unroll
    for (int mt = 0; mt < 4; mt++) {
        const int r0 = rowbase + m_base + mt * 16 + g;
        const int r1 = r0 + 8;
        #pragma unroll
        for (int nt = 0; nt < 8; nt++) {
            const int col = n_base + nt * 8 + tg * 2;
            const float bx = bias_s[col];
            const float by = bias_s[col + 1];
            if (r0 < N_NODES) {
                float2 o = make_float2(acc[mt][nt][0] + bx, acc[mt][nt][1] + by);
                *reinterpret_cast<float2*>(out + (size_t)r0 * OUT_F + col) = o;
            }
            if (r1 < N_NODES) {
                float2 o = make_float2(acc[mt][nt][2] + bx, acc[mt][nt][3] + by);
                *reinterpret_cast<float2*>(out + (size_t)r1 * OUT_F + col) = o;
            }
        }
    }
}

// ---------------------------------------------------------------------------
// Launch
// ---------------------------------------------------------------------------
extern "C" void kernel_launch(void* const* d_in, const int* in_sizes, int n_in,
                              void* d_out, int out_size) {
    const float* x    = (const float*)d_in[0];
    const int*   erow = (const int*)  d_in[1];
    const int*   ecol = (const int*)  d_in[2];
    const float* eval = (const float*)d_in[3];
    const float* W    = (const float*)d_in[4];
    const float* bias = (const float*)d_in[5];
    float* out = (float*)d_out;

    prep_kernel<<<128, 256>>>(W);
    bin_kernel<<<(N_EDGES / 4 + 255) / 256, 256>>>(erow, ecol, eval);
    gather_kernel<<<(N_NODES + 7) / 8, 256>>>(x);

    cudaFuncSetAttribute(gemm_mma_kernel,
                         cudaFuncAttributeMaxDynamicSharedMemorySize, SM_TOT);
    const int gemm_blocks = (N_NODES + 127) / 128;   // 391
    gemm_mma_kernel<<<gemm_blocks, GT, SM_TOT>>>(bias, out);
}

// round 12
// speedup vs baseline: 1.9425x; 1.1342x over previous
#include <cuda_runtime.h>
#include <cuda_fp16.h>
#include <cstdint>

#define N_NODES 50000
#define N_EDGES 800000
#define IN_F    128
#define OUT_F   256
#define PITCH   136   // fp16 per padded row; 68 words mod 32 = 4 -> conflict-free
#define CAP     64
#define OVF_CAP 1024

// ---------------------------------------------------------------------------
// Device scratch (no allocs allowed)
// ---------------------------------------------------------------------------
__device__ __align__(16) __half g_aggh[(size_t)N_NODES * PITCH];  // fp16 agg, padded
__device__ __align__(16) __half g_B[OUT_F * PITCH];               // W^T fp16 image
__device__ int   g_cnt[N_NODES];
__device__ __align__(8)  uint2 g_edge[(size_t)N_NODES * CAP];
__device__ int   g_ovf_cnt;
__device__ __align__(16) uint4 g_ovf[OVF_CAP];

// ---------------------------------------------------------------------------
// K1: zero counts + convert W -> padded fp16 image of W^T.
// ---------------------------------------------------------------------------
__global__ void prep_kernel(const float* __restrict__ W) {
    const int tid = blockIdx.x * blockDim.x + threadIdx.x;
    for (int i = tid; i < N_NODES; i += gridDim.x * blockDim.x) g_cnt[i] = 0;
    if (tid == 0) g_ovf_cnt = 0;

    if (blockIdx.x < 32) {
        const int base = (blockIdx.x * 256 + threadIdx.x) * 4;   // idx = k*256+n
        const float4 w = *reinterpret_cast<const float4*>(W + base);
        const float f[4] = {w.x, w.y, w.z, w.w};
        #pragma unroll
        for (int j = 0; j < 4; j++) {
            const int idx = base + j;
            const int k = idx >> 8;
            const int n = idx & 255;
            g_B[n * PITCH + k] = __float2half(f[j]);
        }
    }
}

// ---------------------------------------------------------------------------
// K2: direct binning — atomic slot claim, 4 edges/thread for ILP.
// ---------------------------------------------------------------------------
__device__ __forceinline__ void bin_one(int r, int c, float v) {
    const int slot = atomicAdd(&g_cnt[r], 1);
    if (slot < CAP) {
        g_edge[(size_t)r * CAP + slot] = make_uint2((uint32_t)c, __float_as_uint(v));
    } else {
        const int p = atomicAdd(&g_ovf_cnt, 1);
        if (p < OVF_CAP)
            g_ovf[p] = make_uint4((uint32_t)r, (uint32_t)c, __float_as_uint(v), 0u);
    }
}

__global__ void bin_kernel(const int*   __restrict__ erow,
                           const int*   __restrict__ ecol,
                           const float* __restrict__ eval) {
    const int base = (blockIdx.x * blockDim.x + threadIdx.x) * 4;
    if (base + 4 <= N_EDGES) {
        const int4   r = __ldg(reinterpret_cast<const int4*>(erow + base));
        const int4   c = __ldg(reinterpret_cast<const int4*>(ecol + base));
        const float4 v = __ldg(reinterpret_cast<const float4*>(eval + base));
        const int s0 = atomicAdd(&g_cnt[r.x], 1);
        const int s1 = atomicAdd(&g_cnt[r.y], 1);
        const int s2 = atomicAdd(&g_cnt[r.z], 1);
        const int s3 = atomicAdd(&g_cnt[r.w], 1);
        if (s0 < CAP) g_edge[(size_t)r.x * CAP + s0] = make_uint2((uint32_t)c.x, __float_as_uint(v.x));
        if (s1 < CAP) g_edge[(size_t)r.y * CAP + s1] = make_uint2((uint32_t)c.y, __float_as_uint(v.y));
        if (s2 < CAP) g_edge[(size_t)r.z * CAP + s2] = make_uint2((uint32_t)c.z, __float_as_uint(v.z));
        if (s3 < CAP) g_edge[(size_t)r.w * CAP + s3] = make_uint2((uint32_t)c.w, __float_as_uint(v.w));
        if (s0 >= CAP) { const int p = atomicAdd(&g_ovf_cnt, 1); if (p < OVF_CAP) g_ovf[p] = make_uint4((uint32_t)r.x, (uint32_t)c.x, __float_as_uint(v.x), 0u); }
        if (s1 >= CAP) { const int p = atomicAdd(&g_ovf_cnt, 1); if (p < OVF_CAP) g_ovf[p] = make_uint4((uint32_t)r.y, (uint32_t)c.y, __float_as_uint(v.y), 0u); }
        if (s2 >= CAP) { const int p = atomicAdd(&g_ovf_cnt, 1); if (p < OVF_CAP) g_ovf[p] = make_uint4((uint32_t)r.z, (uint32_t)c.z, __float_as_uint(v.z), 0u); }
        if (s3 >= CAP) { const int p = atomicAdd(&g_ovf_cnt, 1); if (p < OVF_CAP) g_ovf[p] = make_uint4((uint32_t)r.w, (uint32_t)c.w, __float_as_uint(v.w), 0u); }
    } else {
        for (int e = base; e < N_EDGES; e++)
            bin_one(__ldg(erow + e), __ldg(ecol + e), __ldg(eval + e));
    }
}

// ---------------------------------------------------------------------------
// K3: gather-aggregate. One warp per row; overflow handled inline.
// fp32 accumulate in registers; writes fp16 directly into the padded image.
// ---------------------------------------------------------------------------
__global__ __launch_bounds__(256)
void gather_kernel(const float* __restrict__ x) {
    const int lane = threadIdx.x & 31;
    const int wid  = threadIdx.x >> 5;
    const int row  = blockIdx.x * 8 + wid;
    if (row >= N_NODES) return;

    const int raw_cnt = __ldg(g_cnt + row);
    const int cnt = min(raw_cnt, CAP);
    const size_t base = (size_t)row * CAP;

    float4 acc = make_float4(0.f, 0.f, 0.f, 0.f);

    #pragma unroll
    for (int batch = 0; batch < 2; batch++) {
        const int nb = min(cnt - batch * 32, 32);
        if (nb <= 0) break;
        const uint2 ed = __ldg(g_edge + base + batch * 32 + lane);

        for (int j = 0; j < nb; j += 4) {
            uint32_t c[4];
            float    v[4];
            #pragma unroll
            for (int u = 0; u < 4; u++) {
                const bool valid = (j + u) < nb;
                const uint32_t cc = __shfl_sync(~0u, ed.x, (j + u) & 31);
                const uint32_t vv = __shfl_sync(~0u, ed.y, (j + u) & 31);
                c[u] = valid ? cc : 0u;
                v[u] = valid ? __uint_as_float(vv) : 0.f;
            }
            float4 xv[4];
            #pragma unroll
            for (int u = 0; u < 4; u++)
                xv[u] = __ldg(reinterpret_cast<const float4*>(
                    x + (size_t)c[u] * IN_F) + lane);
            #pragma unroll
            for (int u = 0; u < 4; u++) {
                acc.x += v[u] * xv[u].x;
                acc.y += v[u] * xv[u].y;
                acc.z += v[u] * xv[u].z;
                acc.w += v[u] * xv[u].w;
            }
        }
    }

    if (raw_cnt > CAP) {
        const int n = min(g_ovf_cnt, OVF_CAP);
        for (int i = 0; i < n; i++) {
            const uint4 e = g_ovf[i];
            if ((int)e.x == row) {
                const float v = __uint_as_float(e.z);
                const float4 xv = __ldg(reinterpret_cast<const float4*>(
                    x + (size_t)e.y * IN_F) + lane);
                acc.x += v * xv.x; acc.y += v * xv.y;
                acc.z += v * xv.z; acc.w += v * xv.w;
            }
        }
    }

    // fp16 pack: k = 4*lane .. 4*lane+3 into padded row image.
    uint2 ha;
    __half2 h0 = __floats2half2_rn(acc.x, acc.y);
    __half2 h1 = __floats2half2_rn(acc.z, acc.w);
    ha.x = *reinterpret_cast<uint32_t*>(&h0);
    ha.y = *reinterpret_cast<uint32_t*>(&h1);
    *reinterpret_cast<uint2*>(g_aggh + (size_t)row * PITCH + lane * 4) = ha;
}

// ---------------------------------------------------------------------------
// K4: mma.sync fp16 single-pass GEMM + bias.
//   out = A@B + b    (A, B fp16; fp32 accumulate)
// 256 thr, warp grid 2x4, warp tile 64x64 (pipe-bound; spills irrelevant).
// ---------------------------------------------------------------------------
#define GT 256
#define SM_BIAS 0
#define SM_A    1024
#define SM_B    (SM_A + 128 * PITCH * 2)            // +34816
#define SM_TOT  (SM_B + OUT_F * PITCH * 2)          // 105472 B

__device__ __forceinline__ void mma16816(float c[4], uint32_t a0, uint32_t a1,
                                         uint32_t a2, uint32_t a3,
                                         uint32_t b0, uint32_t b1) {
    asm volatile(
        "mma.sync.aligned.m16n8k16.row.col.f32.f16.f16.f32 "
        "{%0,%1,%2,%3}, {%4,%5,%6,%7}, {%8,%9}, {%0,%1,%2,%3};"
        : "+f"(c[0]), "+f"(c[1]), "+f"(c[2]), "+f"(c[3])
        : "r"(a0), "r"(a1), "r"(a2), "r"(a3), "r"(b0), "r"(b1));
}

__global__ __launch_bounds__(GT, 1)
void gemm_mma_kernel(const float* __restrict__ bias,
                     float*       __restrict__ out) {
    extern __shared__ char smem[];
    const int t    = threadIdx.x;
    const int lane = t & 31;
    const int wid  = t >> 5;
    const int rowbase = blockIdx.x * 128;

    float* bias_s = reinterpret_cast<float*>(smem + SM_BIAS);
    __half* As = reinterpret_cast<__half*>(smem + SM_A);
    __half* Bs = reinterpret_cast<__half*>(smem + SM_B);

    if (t < 64)
        reinterpret_cast<float4*>(bias_s)[t] =
            reinterpret_cast<const float4*>(bias)[t];

    // Copy W^T image: 4352 uint4, 17 per thread.
    {
        const uint4* sb = reinterpret_cast<const uint4*>(g_B);
        uint4* db = reinterpret_cast<uint4*>(Bs);
        #pragma unroll
        for (int i = 0; i < 17; i++)
            db[t + i * GT] = sb[t + i * GT];
    }

    // Stage A: straight uint4 copy of padded fp16 rows (2176 uint4).
    #pragma unroll
    for (int i = 0; i < 9; i++) {
        const int idx = t + i * GT;
        if (idx < 128 * 17) {
            const int m = idx / 17;
            const int c = idx % 17;
            const int row = rowbase + m;
            uint4 val;
            if (row < N_NODES)
                val = *reinterpret_cast<const uint4*>(
                    g_aggh + (size_t)row * PITCH + c * 8);
            else
                val = make_uint4(0u, 0u, 0u, 0u);
            *reinterpret_cast<uint4*>(As + m * PITCH + c * 8) = val;
        }
    }
    __syncthreads();

    // Warp grid 2(m) x 4(n); warp tile 64x64.
    const int wm = wid >> 2;
    const int wn = wid & 3;
    const int g  = lane >> 2;
    const int tg = lane & 3;
    const int m_base = wm * 64;
    const int n_base = wn * 64;

    float acc[4][8][4];
    #pragma unroll
    for (int mt = 0; mt < 4; mt++)
        #pragma unroll
        for (int nt = 0; nt < 8; nt++)
            #pragma unroll
            for (int j = 0; j < 4; j++)
                acc[mt][nt][j] = 0.f;

    #pragma unroll
    for (int ks = 0; ks < IN_F; ks += 16) {
        uint32_t af[4][4];
        #pragma unroll
        for (int mt = 0; mt < 4; mt++) {
            const __half* ar =
                As + (m_base + mt * 16 + g) * PITCH + ks + tg * 2;
            af[mt][0] = *reinterpret_cast<const uint32_t*>(ar);
            af[mt][1] = *reinterpret_cast<const uint32_t*>(ar + 8 * PITCH);
            af[mt][2] = *reinterpret_cast<const uint32_t*>(ar + 8);
            af[mt][3] = *reinterpret_cast<const uint32_t*>(ar + 8 * PITCH + 8);
        }
        uint32_t bf[8][2];
        #pragma unroll
        for (int nt = 0; nt < 8; nt++) {
            const __half* br =
                Bs + (n_base + nt * 8 + g) * PITCH + ks + tg * 2;
            bf[nt][0] = *reinterpret_cast<const uint32_t*>(br);
            bf[nt][1] = *reinterpret_cast<const uint32_t*>(br + 8);
        }
        #pragma unroll
        for (int mt = 0; mt < 4; mt++)
            #pragma unroll
            for (int nt = 0; nt < 8; nt++)
                mma16816(acc[mt][nt],
                         af[mt][0], af[mt][1], af[mt][2], af[mt][3],
                         bf[nt][0], bf[nt][1]);
    }

    // Epilogue: c0:(g,2t) c1:(g,2t+1) c2:(g+8,2t) c3:(g+8,2t+1)
    #pragma unroll
    for (int mt = 0; mt < 4; mt++) {
        const int r0 = rowbase + m_base + mt * 16 + g;
        const int r1 = r0 + 8;
        #pragma unroll
        for (int nt = 0; nt < 8; nt++) {
            const int col = n_base + nt * 8 + tg * 2;
            const float bx = bias_s[col];
            const float by = bias_s[col + 1];
            if (r0 < N_NODES) {
                float2 o = make_float2(acc[mt][nt][0] + bx, acc[mt][nt][1] + by);
                *reinterpret_cast<float2*>(out + (size_t)r0 * OUT_F + col) = o;
            }
            if (r1 < N_NODES) {
                float2 o = make_float2(acc[mt][nt][2] + bx, acc[mt][nt][3] + by);
                *reinterpret_cast<float2*>(out + (size_t)r1 * OUT_F + col) = o;
            }
        }
    }
}

// ---------------------------------------------------------------------------
// Launch
// ---------------------------------------------------------------------------
extern "C" void kernel_launch(void* const* d_in, const int* in_sizes, int n_in,
                              void* d_out, int out_size) {
    const float* x    = (const float*)d_in[0];
    const int*   erow = (const int*)  d_in[1];
    const int*   ecol = (const int*)  d_in[2];
    const float* eval = (const float*)d_in[3];
    const float* W    = (const float*)d_in[4];
    const float* bias = (const float*)d_in[5];
    float* out = (float*)d_out;

    prep_kernel<<<128, 256>>>(W);
    bin_kernel<<<(N_EDGES / 4 + 255) / 256, 256>>>(erow, ecol, eval);
    gather_kernel<<<(N_NODES + 7) / 8, 256>>>(x);

    cudaFuncSetAttribute(gemm_mma_kernel,
                         cudaFuncAttributeMaxDynamicSharedMemorySize, SM_TOT);
    const int gemm_blocks = (N_NODES + 127) / 128;   // 391
    gemm_mma_kernel<<<gemm_blocks, GT, SM_TOT>>>(bias, out);
}

// round 13
// speedup vs baseline: 1.9961x; 1.0276x over previous
#include <cuda_runtime.h>
#include <cuda_fp16.h>
#include <cstdint>

#define N_NODES 50000
#define N_EDGES 800000
#define IN_F    128
#define OUT_F   256
#define PITCH   136   // fp16 per padded row; 68 words mod 32 = 4 -> conflict-free
#define CAP     64
#define OVF_CAP 1024
#define N_TILES ((N_NODES + 127) / 128)   // 391
#define GEMM_GRID 148

// ---------------------------------------------------------------------------
// Device scratch (no allocs allowed)
// ---------------------------------------------------------------------------
__device__ __align__(16) __half g_xh[(size_t)N_NODES * IN_F];     // fp16 x image
__device__ __align__(16) __half g_aggh[(size_t)N_NODES * PITCH]; // fp16 agg, padded
__device__ __align__(16) __half g_B[OUT_F * PITCH];              // W^T fp16 image
__device__ int   g_cnt[N_NODES];
__device__ __align__(8)  uint2 g_edge[(size_t)N_NODES * CAP];
__device__ int   g_ovf_cnt;
__device__ __align__(16) uint4 g_ovf[OVF_CAP];

// ---------------------------------------------------------------------------
// K1: zero counts + convert x -> fp16 image + convert W -> padded fp16 W^T.
// ---------------------------------------------------------------------------
__global__ void prep_kernel(const float* __restrict__ x,
                            const float* __restrict__ W) {
    const int tid = blockIdx.x * blockDim.x + threadIdx.x;
    const int stride = gridDim.x * blockDim.x;

    for (int i = tid; i < N_NODES; i += stride) g_cnt[i] = 0;
    if (tid == 0) g_ovf_cnt = 0;

    // x conversion: 6.4M floats = 1.6M float4 items.
    const int nx4 = (N_NODES * IN_F) / 4;
    for (int i = tid; i < nx4; i += stride) {
        const float4 f = __ldg(reinterpret_cast<const float4*>(x) + i);
        __half2 h0 = __floats2half2_rn(f.x, f.y);
        __half2 h1 = __floats2half2_rn(f.z, f.w);
        uint2 o;
        o.x = *reinterpret_cast<uint32_t*>(&h0);
        o.y = *reinterpret_cast<uint32_t*>(&h1);
        reinterpret_cast<uint2*>(g_xh)[i] = o;
    }

    // W conversion (blocks 0..31 cover 32768 elements).
    if (blockIdx.x < 32) {
        const int base = (blockIdx.x * 256 + threadIdx.x) * 4;   // idx = k*256+n
        const float4 w = *reinterpret_cast<const float4*>(W + base);
        const float f[4] = {w.x, w.y, w.z, w.w};
        #pragma unroll
        for (int j = 0; j < 4; j++) {
            const int idx = base + j;
            const int k = idx >> 8;
            const int n = idx & 255;
            g_B[n * PITCH + k] = __float2half(f[j]);
        }
    }
}

// ---------------------------------------------------------------------------
// K2: direct binning — atomic slot claim, 4 edges/thread for ILP.
// ---------------------------------------------------------------------------
__device__ __forceinline__ void bin_one(int r, int c, float v) {
    const int slot = atomicAdd(&g_cnt[r], 1);
    if (slot < CAP) {
        g_edge[(size_t)r * CAP + slot] = make_uint2((uint32_t)c, __float_as_uint(v));
    } else {
        const int p = atomicAdd(&g_ovf_cnt, 1);
        if (p < OVF_CAP)
            g_ovf[p] = make_uint4((uint32_t)r, (uint32_t)c, __float_as_uint(v), 0u);
    }
}

__global__ void bin_kernel(const int*   __restrict__ erow,
                           const int*   __restrict__ ecol,
                           const float* __restrict__ eval) {
    const int base = (blockIdx.x * blockDim.x + threadIdx.x) * 4;
    if (base + 4 <= N_EDGES) {
        const int4   r = __ldg(reinterpret_cast<const int4*>(erow + base));
        const int4   c = __ldg(reinterpret_cast<const int4*>(ecol + base));
        const float4 v = __ldg(reinterpret_cast<const float4*>(eval + base));
        const int s0 = atomicAdd(&g_cnt[r.x], 1);
        const int s1 = atomicAdd(&g_cnt[r.y], 1);
        const int s2 = atomicAdd(&g_cnt[r.z], 1);
        const int s3 = atomicAdd(&g_cnt[r.w], 1);
        if (s0 < CAP) g_edge[(size_t)r.x * CAP + s0] = make_uint2((uint32_t)c.x, __float_as_uint(v.x));
        if (s1 < CAP) g_edge[(size_t)r.y * CAP + s1] = make_uint2((uint32_t)c.y, __float_as_uint(v.y));
        if (s2 < CAP) g_edge[(size_t)r.z * CAP + s2] = make_uint2((uint32_t)c.z, __float_as_uint(v.z));
        if (s3 < CAP) g_edge[(size_t)r.w * CAP + s3] = make_uint2((uint32_t)c.w, __float_as_uint(v.w));
        if (s0 >= CAP) { const int p = atomicAdd(&g_ovf_cnt, 1); if (p < OVF_CAP) g_ovf[p] = make_uint4((uint32_t)r.x, (uint32_t)c.x, __float_as_uint(v.x), 0u); }
        if (s1 >= CAP) { const int p = atomicAdd(&g_ovf_cnt, 1); if (p < OVF_CAP) g_ovf[p] = make_uint4((uint32_t)r.y, (uint32_t)c.y, __float_as_uint(v.y), 0u); }
        if (s2 >= CAP) { const int p = atomicAdd(&g_ovf_cnt, 1); if (p < OVF_CAP) g_ovf[p] = make_uint4((uint32_t)r.z, (uint32_t)c.z, __float_as_uint(v.z), 0u); }
        if (s3 >= CAP) { const int p = atomicAdd(&g_ovf_cnt, 1); if (p < OVF_CAP) g_ovf[p] = make_uint4((uint32_t)r.w, (uint32_t)c.w, __float_as_uint(v.w), 0u); }
    } else {
        for (int e = base; e < N_EDGES; e++)
            bin_one(__ldg(erow + e), __ldg(ecol + e), __ldg(eval + e));
    }
}

// ---------------------------------------------------------------------------
// K3: gather-aggregate over fp16 x. One warp per row; fp32 accumulate;
// writes fp16 padded agg image. Overflow handled inline.
// ---------------------------------------------------------------------------
__global__ __launch_bounds__(256)
void gather_kernel() {
    const int lane = threadIdx.x & 31;
    const int wid  = threadIdx.x >> 5;
    const int row  = blockIdx.x * 8 + wid;
    if (row >= N_NODES) return;

    const int raw_cnt = __ldg(g_cnt + row);
    const int cnt = min(raw_cnt, CAP);
    const size_t base = (size_t)row * CAP;

    float4 acc = make_float4(0.f, 0.f, 0.f, 0.f);

    #pragma unroll
    for (int batch = 0; batch < 2; batch++) {
        const int nb = min(cnt - batch * 32, 32);
        if (nb <= 0) break;
        const uint2 ed = __ldg(g_edge + base + batch * 32 + lane);

        for (int j = 0; j < nb; j += 4) {
            uint32_t c[4];
            float    v[4];
            #pragma unroll
            for (int u = 0; u < 4; u++) {
                const bool valid = (j + u) < nb;
                const uint32_t cc = __shfl_sync(~0u, ed.x, (j + u) & 31);
                const uint32_t vv = __shfl_sync(~0u, ed.y, (j + u) & 31);
                c[u] = valid ? cc : 0u;
                v[u] = valid ? __uint_as_float(vv) : 0.f;
            }
            uint2 xv[4];
            #pragma unroll
            for (int u = 0; u < 4; u++)
                xv[u] = __ldg(reinterpret_cast<const uint2*>(
                    g_xh + (size_t)c[u] * IN_F) + lane);
            #pragma unroll
            for (int u = 0; u < 4; u++) {
                const float2 f0 = __half22float2(
                    *reinterpret_cast<const __half2*>(&xv[u].x));
                const float2 f1 = __half22float2(
                    *reinterpret_cast<const __half2*>(&xv[u].y));
                acc.x += v[u] * f0.x;
                acc.y += v[u] * f0.y;
                acc.z += v[u] * f1.x;
                acc.w += v[u] * f1.y;
            }
        }
    }

    if (raw_cnt > CAP) {
        const int n = min(g_ovf_cnt, OVF_CAP);
        for (int i = 0; i < n; i++) {
            const uint4 e = g_ovf[i];
            if ((int)e.x == row) {
                const float v = __uint_as_float(e.z);
                const uint2 xv = __ldg(reinterpret_cast<const uint2*>(
                    g_xh + (size_t)e.y * IN_F) + lane);
                const float2 f0 = __half22float2(
                    *reinterpret_cast<const __half2*>(&xv.x));
                const float2 f1 = __half22float2(
                    *reinterpret_cast<const __half2*>(&xv.y));
                acc.x += v * f0.x; acc.y += v * f0.y;
                acc.z += v * f1.x; acc.w += v * f1.y;
            }
        }
    }

    uint2 ha;
    __half2 h0 = __floats2half2_rn(acc.x, acc.y);
    __half2 h1 = __floats2half2_rn(acc.z, acc.w);
    ha.x = *reinterpret_cast<uint32_t*>(&h0);
    ha.y = *reinterpret_cast<uint32_t*>(&h1);
    *reinterpret_cast<uint2*>(g_aggh + (size_t)row * PITCH + lane * 4) = ha;
}

// ---------------------------------------------------------------------------
// K4: persistent mma.sync fp16 single-pass GEMM + bias.
// Grid = 148 (single wave, 1 CTA/SM). B image + bias staged once per CTA;
// tile loop over 391 M-tiles reuses them.
// ---------------------------------------------------------------------------
#define GT 256
#define SM_BIAS 0
#define SM_A    1024
#define SM_B    (SM_A + 128 * PITCH * 2)            // +34816
#define SM_TOT  (SM_B + OUT_F * PITCH * 2)          // 105472 B

__device__ __forceinline__ void mma16816(float c[4], uint32_t a0, uint32_t a1,
                                         uint32_t a2, uint32_t a3,
                                         uint32_t b0, uint32_t b1) {
    asm volatile(
        "mma.sync.aligned.m16n8k16.row.col.f32.f16.f16.f32 "
        "{%0,%1,%2,%3}, {%4,%5,%6,%7}, {%8,%9}, {%0,%1,%2,%3};"
        : "+f"(c[0]), "+f"(c[1]), "+f"(c[2]), "+f"(c[3])
        : "r"(a0), "r"(a1), "r"(a2), "r"(a3), "r"(b0), "r"(b1));
}

__global__ __launch_bounds__(GT, 1)
void gemm_mma_kernel(const float* __restrict__ bias,
                     float*       __restrict__ out) {
    extern __shared__ char smem[];
    const int t    = threadIdx.x;
    const int lane = t & 31;
    const int wid  = t >> 5;

    float* bias_s = reinterpret_cast<float*>(smem + SM_BIAS);
    __half* As = reinterpret_cast<__half*>(smem + SM_A);
    __half* Bs = reinterpret_cast<__half*>(smem + SM_B);

    if (t < 64)
        reinterpret_cast<float4*>(bias_s)[t] =
            reinterpret_cast<const float4*>(bias)[t];

    // Stage W^T image once per CTA: 4352 uint4, 17 per thread.
    {
        const uint4* sb = reinterpret_cast<const uint4*>(g_B);
        uint4* db = reinterpret_cast<uint4*>(Bs);
        #pragma unroll
        for (int i = 0; i < 17; i++)
            db[t + i * GT] = sb[t + i * GT];
    }

    // Warp grid 2(m) x 4(n); warp tile 64x64.
    const int wm = wid >> 2;
    const int wn = wid & 3;
    const int g  = lane >> 2;
    const int tg = lane & 3;
    const int m_base = wm * 64;
    const int n_base = wn * 64;

    for (int tile = blockIdx.x; tile < N_TILES; tile += GEMM_GRID) {
        const int rowbase = tile * 128;

        // Stage A: straight uint4 copy of padded fp16 rows (2176 uint4).
        #pragma unroll
        for (int i = 0; i < 9; i++) {
            const int idx = t + i * GT;
            if (idx < 128 * 17) {
                const int m = idx / 17;
                const int c = idx % 17;
                const int row = rowbase + m;
                uint4 val;
                if (row < N_NODES)
                    val = *reinterpret_cast<const uint4*>(
                        g_aggh + (size_t)row * PITCH + c * 8);
                else
                    val = make_uint4(0u, 0u, 0u, 0u);
                *reinterpret_cast<uint4*>(As + m * PITCH + c * 8) = val;
            }
        }
        __syncthreads();

        float acc[4][8][4];
        #pragma unroll
        for (int mt = 0; mt < 4; mt++)
            #pragma unroll
            for (int nt = 0; nt < 8; nt++)
                #pragma unroll
                for (int j = 0; j < 4; j++)
                    acc[mt][nt][j] = 0.f;

        #pragma unroll
        for (int ks = 0; ks < IN_F; ks += 16) {
            uint32_t af[4][4];
            #pragma unroll
            for (int mt = 0; mt < 4; mt++) {
                const __half* ar =
                    As + (m_base + mt * 16 + g) * PITCH + ks + tg * 2;
                af[mt][0] = *reinterpret_cast<const uint32_t*>(ar);
                af[mt][1] = *reinterpret_cast<const uint32_t*>(ar + 8 * PITCH);
                af[mt][2] = *reinterpret_cast<const uint32_t*>(ar + 8);
                af[mt][3] = *reinterpret_cast<const uint32_t*>(ar + 8 * PITCH + 8);
            }
            uint32_t bf[8][2];
            #pragma unroll
            for (int nt = 0; nt < 8; nt++) {
                const __half* br =
                    Bs + (n_base + nt * 8 + g) * PITCH + ks + tg * 2;
                bf[nt][0] = *reinterpret_cast<const uint32_t*>(br);
                bf[nt][1] = *reinterpret_cast<const uint32_t*>(br + 8);
            }
            #pragma unroll
            for (int mt = 0; mt < 4; mt++)
                #pragma unroll
                for (int nt = 0; nt < 8; nt++)
                    mma16816(acc[mt][nt],
                             af[mt][0], af[mt][1], af[mt][2], af[mt][3],
                             bf[nt][0], bf[nt][1]);
        }

        // Epilogue
        #pragma unroll
        for (int mt = 0; mt < 4; mt++) {
            const int r0 = rowbase + m_base + mt * 16 + g;
            const int r1 = r0 + 8;
            #pragma unroll
            for (int nt = 0; nt < 8; nt++) {
                const int col = n_base + nt * 8 + tg * 2;
                const float bx = bias_s[col];
                const float by = bias_s[col + 1];
                if (r0 < N_NODES) {
                    float2 o = make_float2(acc[mt][nt][0] + bx, acc[mt][nt][1] + by);
                    *reinterpret_cast<float2*>(out + (size_t)r0 * OUT_F + col) = o;
                }
                if (r1 < N_NODES) {
                    float2 o = make_float2(acc[mt][nt][2] + bx, acc[mt][nt][3] + by);
                    *reinterpret_cast<float2*>(out + (size_t)r1 * OUT_F + col) = o;
                }
            }
        }
        __syncthreads();   // protect As reuse next tile
    }
}

// ---------------------------------------------------------------------------
// Launch
// ---------------------------------------------------------------------------
extern "C" void kernel_launch(void* const* d_in, const int* in_sizes, int n_in,
                              void* d_out, int out_size) {
    const float* x    = (const float*)d_in[0];
    const int*   erow = (const int*)  d_in[1];
    const int*   ecol = (const int*)  d_in[2];
    const float* eval = (const float*)d_in[3];
    const float* W    = (const float*)d_in[4];
    const float* bias = (const float*)d_in[5];
    float* out = (float*)d_out;

    prep_kernel<<<2048, 256>>>(x, W);
    bin_kernel<<<(N_EDGES / 4 + 255) / 256, 256>>>(erow, ecol, eval);
    gather_kernel<<<(N_NODES + 7) / 8, 256>>>();

    cudaFuncSetAttribute(gemm_mma_kernel,
                         cudaFuncAttributeMaxDynamicSharedMemorySize, SM_TOT);
    gemm_mma_kernel<<<GEMM_GRID, GT, SM_TOT>>>(bias, out);
}

// round 14
// speedup vs baseline: 2.0527x; 1.0284x over previous
#include <cuda_runtime.h>
#include <cuda_fp16.h>
#include <cstdint>

#define N_NODES 50000
#define N_EDGES 800000
#define IN_F    128
#define OUT_F   256
#define PITCH   136   // fp16 per padded row; 68 words mod 32 = 4 -> conflict-free
#define CAP     64
#define OVF_CAP 1024
#define N_TILES ((N_NODES + 127) / 128)   // 391
#define GEMM_GRID 148
#define BIN_BLOCKS 782                     // 782*256*4 >= 800k edges
#define CONV_BLOCKS 1568

// ---------------------------------------------------------------------------
// Device scratch (no allocs allowed)
// ---------------------------------------------------------------------------
__device__ __align__(16) __half g_xh[(size_t)N_NODES * IN_F];    // fp16 x image
__device__ __align__(16) __half g_aggh[(size_t)N_NODES * PITCH]; // fp16 agg, padded
__device__ __align__(16) __half g_B[OUT_F * PITCH];              // W^T fp16 image
__device__ int   g_cnt[N_NODES];
__device__ __align__(8)  uint2 g_edge[(size_t)N_NODES * CAP];
__device__ int   g_ovf_cnt;
__device__ __align__(16) uint4 g_ovf[OVF_CAP];

// ---------------------------------------------------------------------------
// K1: zero counts + convert W -> padded fp16 W^T image. (fast)
// ---------------------------------------------------------------------------
__global__ void prep_kernel(const float* __restrict__ W) {
    const int tid = blockIdx.x * blockDim.x + threadIdx.x;
    for (int i = tid; i < N_NODES; i += gridDim.x * blockDim.x) g_cnt[i] = 0;
    if (tid == 0) g_ovf_cnt = 0;

    if (blockIdx.x < 32) {
        const int base = (blockIdx.x * 256 + threadIdx.x) * 4;   // idx = k*256+n
        const float4 w = *reinterpret_cast<const float4*>(W + base);
        const float f[4] = {w.x, w.y, w.z, w.w};
        #pragma unroll
        for (int j = 0; j < 4; j++) {
            const int idx = base + j;
            const int k = idx >> 8;
            const int n = idx & 255;
            g_B[n * PITCH + k] = __float2half(f[j]);
        }
    }
}

// ---------------------------------------------------------------------------
// K2: binning (blocks [0,BIN_BLOCKS)) CONCURRENT WITH x fp16 conversion
// (blocks [BIN_BLOCKS, BIN_BLOCKS+CONV_BLOCKS)) — independent work overlapped
// in one launch.
// ---------------------------------------------------------------------------
__device__ __forceinline__ void bin_one(int r, int c, float v) {
    const int slot = atomicAdd(&g_cnt[r], 1);
    if (slot < CAP) {
        g_edge[(size_t)r * CAP + slot] = make_uint2((uint32_t)c, __float_as_uint(v));
    } else {
        const int p = atomicAdd(&g_ovf_cnt, 1);
        if (p < OVF_CAP)
            g_ovf[p] = make_uint4((uint32_t)r, (uint32_t)c, __float_as_uint(v), 0u);
    }
}

__global__ void bin_conv_kernel(const int*   __restrict__ erow,
                                const int*   __restrict__ ecol,
                                const float* __restrict__ eval,
                                const float* __restrict__ x) {
    if (blockIdx.x < BIN_BLOCKS) {
        const int base = (blockIdx.x * blockDim.x + threadIdx.x) * 4;
        if (base + 4 <= N_EDGES) {
            const int4   r = __ldg(reinterpret_cast<const int4*>(erow + base));
            const int4   c = __ldg(reinterpret_cast<const int4*>(ecol + base));
            const float4 v = __ldg(reinterpret_cast<const float4*>(eval + base));
            const int s0 = atomicAdd(&g_cnt[r.x], 1);
            const int s1 = atomicAdd(&g_cnt[r.y], 1);
            const int s2 = atomicAdd(&g_cnt[r.z], 1);
            const int s3 = atomicAdd(&g_cnt[r.w], 1);
            if (s0 < CAP) g_edge[(size_t)r.x * CAP + s0] = make_uint2((uint32_t)c.x, __float_as_uint(v.x));
            if (s1 < CAP) g_edge[(size_t)r.y * CAP + s1] = make_uint2((uint32_t)c.y, __float_as_uint(v.y));
            if (s2 < CAP) g_edge[(size_t)r.z * CAP + s2] = make_uint2((uint32_t)c.z, __float_as_uint(v.z));
            if (s3 < CAP) g_edge[(size_t)r.w * CAP + s3] = make_uint2((uint32_t)c.w, __float_as_uint(v.w));
            if (s0 >= CAP) { const int p = atomicAdd(&g_ovf_cnt, 1); if (p < OVF_CAP) g_ovf[p] = make_uint4((uint32_t)r.x, (uint32_t)c.x, __float_as_uint(v.x), 0u); }
            if (s1 >= CAP) { const int p = atomicAdd(&g_ovf_cnt, 1); if (p < OVF_CAP) g_ovf[p] = make_uint4((uint32_t)r.y, (uint32_t)c.y, __float_as_uint(v.y), 0u); }
            if (s2 >= CAP) { const int p = atomicAdd(&g_ovf_cnt, 1); if (p < OVF_CAP) g_ovf[p] = make_uint4((uint32_t)r.z, (uint32_t)c.z, __float_as_uint(v.z), 0u); }
            if (s3 >= CAP) { const int p = atomicAdd(&g_ovf_cnt, 1); if (p < OVF_CAP) g_ovf[p] = make_uint4((uint32_t)r.w, (uint32_t)c.w, __float_as_uint(v.w), 0u); }
        } else {
            for (int e = base; e < N_EDGES; e++)
                bin_one(__ldg(erow + e), __ldg(ecol + e), __ldg(eval + e));
        }
    } else {
        // x conversion: 1.6M float4 items over CONV_BLOCKS*256 threads.
        const int cid = (blockIdx.x - BIN_BLOCKS) * blockDim.x + threadIdx.x;
        const int n4 = (N_NODES * IN_F) / 4;
        for (int i = cid; i < n4; i += CONV_BLOCKS * 256) {
            const float4 f = __ldg(reinterpret_cast<const float4*>(x) + i);
            __half2 h0 = __floats2half2_rn(f.x, f.y);
            __half2 h1 = __floats2half2_rn(f.z, f.w);
            uint2 o;
            o.x = *reinterpret_cast<uint32_t*>(&h0);
            o.y = *reinterpret_cast<uint32_t*>(&h1);
            reinterpret_cast<uint2*>(g_xh)[i] = o;
        }
    }
}

// ---------------------------------------------------------------------------
// K3: gather-aggregate over fp16 x. One warp per row; 8-wide unrolled edge
// groups (MLP 8). fp32 accumulate; writes fp16 padded agg image.
// ---------------------------------------------------------------------------
__global__ __launch_bounds__(256)
void gather_kernel() {
    const int lane = threadIdx.x & 31;
    const int wid  = threadIdx.x >> 5;
    const int row  = blockIdx.x * 8 + wid;
    if (row >= N_NODES) return;

    const int raw_cnt = __ldg(g_cnt + row);
    const int cnt = min(raw_cnt, CAP);
    const size_t base = (size_t)row * CAP;

    float4 acc = make_float4(0.f, 0.f, 0.f, 0.f);

    #pragma unroll
    for (int batch = 0; batch < 2; batch++) {
        const int nb = min(cnt - batch * 32, 32);
        if (nb <= 0) break;
        const uint2 ed = __ldg(g_edge + base + batch * 32 + lane);

        for (int j = 0; j < nb; j += 8) {
            uint32_t c[8];
            float    v[8];
            #pragma unroll
            for (int u = 0; u < 8; u++) {
                const bool valid = (j + u) < nb;
                const uint32_t cc = __shfl_sync(~0u, ed.x, (j + u) & 31);
                const uint32_t vv = __shfl_sync(~0u, ed.y, (j + u) & 31);
                c[u] = valid ? cc : 0u;
                v[u] = valid ? __uint_as_float(vv) : 0.f;
            }
            uint2 xv[8];
            #pragma unroll
            for (int u = 0; u < 8; u++)
                xv[u] = __ldg(reinterpret_cast<const uint2*>(
                    g_xh + (size_t)c[u] * IN_F) + lane);
            #pragma unroll
            for (int u = 0; u < 8; u++) {
                const float2 f0 = __half22float2(
                    *reinterpret_cast<const __half2*>(&xv[u].x));
                const float2 f1 = __half22float2(
                    *reinterpret_cast<const __half2*>(&xv[u].y));
                acc.x += v[u] * f0.x;
                acc.y += v[u] * f0.y;
                acc.z += v[u] * f1.x;
                acc.w += v[u] * f1.y;
            }
        }
    }

    if (raw_cnt > CAP) {
        const int n = min(g_ovf_cnt, OVF_CAP);
        for (int i = 0; i < n; i++) {
            const uint4 e = g_ovf[i];
            if ((int)e.x == row) {
                const float v = __uint_as_float(e.z);
                const uint2 xv = __ldg(reinterpret_cast<const uint2*>(
                    g_xh + (size_t)e.y * IN_F) + lane);
                const float2 f0 = __half22float2(
                    *reinterpret_cast<const __half2*>(&xv.x));
                const float2 f1 = __half22float2(
                    *reinterpret_cast<const __half2*>(&xv.y));
                acc.x += v * f0.x; acc.y += v * f0.y;
                acc.z += v * f1.x; acc.w += v * f1.y;
            }
        }
    }

    uint2 ha;
    __half2 h0 = __floats2half2_rn(acc.x, acc.y);
    __half2 h1 = __floats2half2_rn(acc.z, acc.w);
    ha.x = *reinterpret_cast<uint32_t*>(&h0);
    ha.y = *reinterpret_cast<uint32_t*>(&h1);
    *reinterpret_cast<uint2*>(g_aggh + (size_t)row * PITCH + lane * 4) = ha;
}

// ---------------------------------------------------------------------------
// K4: persistent mma.sync fp16 GEMM + bias, double-buffered A via cp.async.
// ---------------------------------------------------------------------------
#define GT 256
#define SM_BIAS 0
#define SM_A0   1024
#define SM_A1   (SM_A0 + 128 * PITCH * 2)           // +34816
#define SM_B    (SM_A1 + 128 * PITCH * 2)
#define SM_TOT  (SM_B + OUT_F * PITCH * 2)          // 140288 B

__device__ __forceinline__ void mma16816(float c[4], uint32_t a0, uint32_t a1,
                                         uint32_t a2, uint32_t a3,
                                         uint32_t b0, uint32_t b1) {
    asm volatile(
        "mma.sync.aligned.m16n8k16.row.col.f32.f16.f16.f32 "
        "{%0,%1,%2,%3}, {%4,%5,%6,%7}, {%8,%9}, {%0,%1,%2,%3};"
        : "+f"(c[0]), "+f"(c[1]), "+f"(c[2]), "+f"(c[3])
        : "r"(a0), "r"(a1), "r"(a2), "r"(a3), "r"(b0), "r"(b1));
}

__device__ __forceinline__ uint32_t smem_u32(const void* p) {
    uint32_t a;
    asm("{ .reg .u64 t; cvta.to.shared.u64 t, %1; cvt.u32.u64 %0, t; }"
        : "=r"(a) : "l"(p));
    return a;
}

// Prefetch one A tile (2176 x 16B) into smem buffer via cp.async (zfill OOB).
__device__ __forceinline__ void stage_a_async(uint32_t sm_dst, int rowbase, int t) {
    #pragma unroll
    for (int i = 0; i < 9; i++) {
        const int idx = t + i * GT;
        if (idx < 128 * 17) {
            const int m = idx / 17;
            const int c = idx % 17;
            const int row = rowbase + m;
            const int sz = (row < N_NODES) ? 16 : 0;
            const __half* src = g_aggh +
                (size_t)(row < N_NODES ? row : 0) * PITCH + c * 8;
            const uint32_t dst = sm_dst + m * (PITCH * 2) + c * 16;
            asm volatile("cp.async.cg.shared.global [%0], [%1], 16, %2;"
                         :: "r"(dst), "l"(src), "r"(sz) : "memory");
        }
    }
    asm volatile("cp.async.commit_group;" ::: "memory");
}

__global__ __launch_bounds__(GT, 1)
void gemm_mma_kernel(const float* __restrict__ bias,
                     float*       __restrict__ out) {
    extern __shared__ char smem[];
    const int t    = threadIdx.x;
    const int lane = t & 31;
    const int wid  = t >> 5;

    float* bias_s = reinterpret_cast<float*>(smem + SM_BIAS);
    __half* Bs = reinterpret_cast<__half*>(smem + SM_B);
    const uint32_t smA[2] = {smem_u32(smem + SM_A0), smem_u32(smem + SM_A1)};
    __half* const Ap[2] = {reinterpret_cast<__half*>(smem + SM_A0),
                           reinterpret_cast<__half*>(smem + SM_A1)};

    // Prefetch first tile's A.
    if (blockIdx.x < N_TILES)
        stage_a_async(smA[0], blockIdx.x * 128, t);

    if (t < 64)
        reinterpret_cast<float4*>(bias_s)[t] =
            reinterpret_cast<const float4*>(bias)[t];

    // Stage W^T image once per CTA: 4352 uint4, 17 per thread.
    {
        const uint4* sb = reinterpret_cast<const uint4*>(g_B);
        uint4* db = reinterpret_cast<uint4*>(Bs);
        #pragma unroll
        for (int i = 0; i < 17; i++)
            db[t + i * GT] = sb[t + i * GT];
    }

    asm volatile("cp.async.wait_group 0;" ::: "memory");
    __syncthreads();

    // Warp grid 2(m) x 4(n); warp tile 64x64.
    const int wm = wid >> 2;
    const int wn = wid & 3;
    const int g  = lane >> 2;
    const int tg = lane & 3;
    const int m_base = wm * 64;
    const int n_base = wn * 64;

    int cur = 0;
    for (int tile = blockIdx.x; tile < N_TILES; tile += GEMM_GRID) {
        const int rowbase = tile * 128;

        // Prefetch next tile's A into the alternate buffer (overlaps mainloop).
        const int next = tile + GEMM_GRID;
        if (next < N_TILES)
            stage_a_async(smA[cur ^ 1], next * 128, t);

        const __half* As = Ap[cur];

        float acc[4][8][4];
        #pragma unroll
        for (int mt = 0; mt < 4; mt++)
            #pragma unroll
            for (int nt = 0; nt < 8; nt++)
                #pragma unroll
                for (int j = 0; j < 4; j++)
                    acc[mt][nt][j] = 0.f;

        #pragma unroll
        for (int ks = 0; ks < IN_F; ks += 16) {
            uint32_t af[4][4];
            #pragma unroll
            for (int mt = 0; mt < 4; mt++) {
                const __half* ar =
                    As + (m_base + mt * 16 + g) * PITCH + ks + tg * 2;
                af[mt][0] = *reinterpret_cast<const uint32_t*>(ar);
                af[mt][1] = *reinterpret_cast<const uint32_t*>(ar + 8 * PITCH);
                af[mt][2] = *reinterpret_cast<const uint32_t*>(ar + 8);
                af[mt][3] = *reinterpret_cast<const uint32_t*>(ar + 8 * PITCH + 8);
            }
            uint32_t bf[8][2];
            #pragma unroll
            for (int nt = 0; nt < 8; nt++) {
                const __half* br =
                    Bs + (n_base + nt * 8 + g) * PITCH + ks + tg * 2;
                bf[nt][0] = *reinterpret_cast<const uint32_t*>(br);
                bf[nt][1] = *reinterpret_cast<const uint32_t*>(br + 8);
            }
            #pragma unroll
            for (int mt = 0; mt < 4; mt++)
                #pragma unroll
                for (int nt = 0; nt < 8; nt++)
                    mma16816(acc[mt][nt],
                             af[mt][0], af[mt][1], af[mt][2], af[mt][3],
                             bf[nt][0], bf[nt][1]);
        }

        // Epilogue
        #pragma unroll
        for (int mt = 0; mt < 4; mt++) {
            const int r0 = rowbase + m_base + mt * 16 + g;
            const int r1 = r0 + 8;
            #pragma unroll
            for (int nt = 0; nt < 8; nt++) {
                const int col = n_base + nt * 8 + tg * 2;
                const float bx = bias_s[col];
                const float by = bias_s[col + 1];
                if (r0 < N_NODES) {
                    float2 o = make_float2(acc[mt][nt][0] + bx, acc[mt][nt][1] + by);
                    *reinterpret_cast<float2*>(out + (size_t)r0 * OUT_F + col) = o;
                }
                if (r1 < N_NODES) {
                    float2 o = make_float2(acc[mt][nt][2] + bx, acc[mt][nt][3] + by);
                    *reinterpret_cast<float2*>(out + (size_t)r1 * OUT_F + col) = o;
                }
            }
        }

        asm volatile("cp.async.wait_group 0;" ::: "memory");
        __syncthreads();
        cur ^= 1;
    }
}

// ---------------------------------------------------------------------------
// Launch
// ---------------------------------------------------------------------------
extern "C" void kernel_launch(void* const* d_in, const int* in_sizes, int n_in,
                              void* d_out, int out_size) {
    const float* x    = (const float*)d_in[0];
    const int*   erow = (const int*)  d_in[1];
    const int*   ecol = (const int*)  d_in[2];
    const float* eval = (const float*)d_in[3];
    const float* W    = (const float*)d_in[4];
    const float* bias = (const float*)d_in[5];
    float* out = (float*)d_out;

    prep_kernel<<<128, 256>>>(W);
    bin_conv_kernel<<<BIN_BLOCKS + CONV_BLOCKS, 256>>>(erow, ecol, eval, x);
    gather_kernel<<<(N_NODES + 7) / 8, 256>>>();

    cudaFuncSetAttribute(gemm_mma_kernel,
                         cudaFuncAttributeMaxDynamicSharedMemorySize, SM_TOT);
    gemm_mma_kernel<<<GEMM_GRID, GT, SM_TOT>>>(bias, out);
}